// round 1
// baseline (speedup 1.0000x reference)
#include <cuda_runtime.h>
#include <math.h>

#define Bn 16
#define Cn 64
#define Hn 128
#define Wn 128
#define MXn 24
#define MYn 24
#define HIDn 32

// ---------------- scratch (device globals; no runtime allocation) ----------
__device__ float g_xw_re[Bn*Cn*Hn*MYn];       // [b][c][h][ky]
__device__ float g_xw_im[Bn*Cn*Hn*MYn];
__device__ float g_xft_re[MXn*MYn*Bn*Cn];     // [(kx*24+ky)][b][c]
__device__ float g_xft_im[MXn*MYn*Bn*Cn];
__device__ float g_oft_re[MXn*MYn*Bn*Cn];     // [(kx*24+ky)][b][o]
__device__ float g_oft_im[MXn*MYn*Bn*Cn];
__device__ float g_S_re[Bn*Hn*Cn*MYn];        // [b][h][o][ky]  (scaled)
__device__ float g_S_im[Bn*Hn*Cn*MYn];
__device__ float g_cos[MYn*Wn];               // cos(2*pi*k*w/128)
__device__ float g_sin[MYn*Wn];               // sin(2*pi*k*w/128)
__device__ float g_twT[Wn*48];                // [w][j] j<24: cos, j>=24: -sin

// ---------------- K0: twiddle init ----------------
__global__ void k0_init() {
    int i = blockIdx.x*blockDim.x + threadIdx.x;
    if (i >= MYn*Wn) return;
    int k = i / Wn, w = i % Wn;
    float s, c;
    sincospif((float)(k*w) / 64.0f, &s, &c);   // angle = 2*pi*k*w/128 = pi*(k*w/64)
    g_cos[k*Wn + w] = c;
    g_sin[k*Wn + w] = s;
    g_twT[w*48 + k]      = c;
    g_twT[w*48 + 24 + k] = -s;
}

// ---------------- K1: partial DFT over W (GEMM 131072x128 @ 128x48) -------
__global__ void __launch_bounds__(384) k1_dftW(const float* __restrict__ x) {
    __shared__ float Xs[32*132];   // [kk][row], padded
    __shared__ float Tw[32*48];    // [kk][j]
    int tid = threadIdx.x;
    int rg = tid & 31;         // row group: rows 4*rg..4*rg+3
    int jg = tid >> 5;         // col group: cols 4*jg..4*jg+3 (jg in [0,12))
    int row0 = blockIdx.x * 128;

    float acc[4][4];
    #pragma unroll
    for (int i = 0; i < 4; i++)
        #pragma unroll
        for (int j = 0; j < 4; j++) acc[i][j] = 0.f;

    for (int kt = 0; kt < 4; kt++) {
        for (int i = tid; i < 4096; i += 384) {
            int r = i >> 5, w = i & 31;
            Xs[w*132 + r] = x[(size_t)(row0 + r)*128 + kt*32 + w];
        }
        for (int i = tid; i < 32*48; i += 384)
            Tw[i] = g_twT[kt*32*48 + i];
        __syncthreads();
        #pragma unroll
        for (int kk = 0; kk < 32; kk++) {
            float xv[4], tv[4];
            *(float4*)xv = *(const float4*)&Xs[kk*132 + 4*rg];
            *(float4*)tv = *(const float4*)&Tw[kk*48 + 4*jg];
            #pragma unroll
            for (int i = 0; i < 4; i++)
                #pragma unroll
                for (int j = 0; j < 4; j++)
                    acc[i][j] += xv[i]*tv[j];
        }
        __syncthreads();
    }

    float* dst = (jg < 6) ? g_xw_re : g_xw_im;
    int col = (jg < 6) ? (4*jg) : (4*jg - 24);
    #pragma unroll
    for (int i = 0; i < 4; i++) {
        int r = row0 + 4*rg + i;
        float4 v = make_float4(acc[i][0], acc[i][1], acc[i][2], acc[i][3]);
        *(float4*)&dst[(size_t)r*24 + col] = v;
    }
}

// ---------------- K2: partial DFT over H ----------------
__global__ void __launch_bounds__(288) k2_dftH() {
    __shared__ float xr[128*24], xi[128*24];
    __shared__ float cs[24*128], sn[24*128];
    int bc = blockIdx.x;          // b*64 + c
    int tid = threadIdx.x;
    size_t base = (size_t)bc * (128*24);
    for (int i = tid; i < 3072; i += 288) {
        xr[i] = g_xw_re[base + i];
        xi[i] = g_xw_im[base + i];
        cs[i] = g_cos[i];
        sn[i] = g_sin[i];
    }
    __syncthreads();

    int ky  = tid % 24;
    int kxg = tid / 24;           // 0..11
    int kx0 = 2*kxg, kx1 = 2*kxg + 1;
    float re0 = 0.f, im0 = 0.f, re1 = 0.f, im1 = 0.f;
    for (int h = 0; h < 128; h++) {
        float a = xr[h*24 + ky];
        float b = xi[h*24 + ky];
        float c0 = cs[kx0*128 + h], s0 = sn[kx0*128 + h];
        float c1 = cs[kx1*128 + h], s1 = sn[kx1*128 + h];
        re0 += a*c0 + b*s0;  im0 += b*c0 - a*s0;   // * e^{-i theta}
        re1 += a*c1 + b*s1;  im1 += b*c1 - a*s1;
    }
    int b = bc >> 6, c = bc & 63;
    int m0 = kx0*24 + ky, m1 = kx1*24 + ky;
    g_xft_re[(m0*Bn + b)*Cn + c] = re0;
    g_xft_im[(m0*Bn + b)*Cn + c] = im0;
    g_xft_re[(m1*Bn + b)*Cn + c] = re1;
    g_xft_im[(m1*Bn + b)*Cn + c] = im1;
}

// ---------------- K3: per-mode complex channel mix ----------------
__global__ void __launch_bounds__(256) k3_mix(const float* __restrict__ wr_g,
                                              const float* __restrict__ wi_g) {
    __shared__ float xr_s[1024], xi_s[1024];
    __shared__ float wr_s[4096], wi_s[4096];
    int m = blockIdx.x, tid = threadIdx.x;
    for (int i = tid; i < 1024; i += 256) {
        xr_s[i] = g_xft_re[m*1024 + i];
        xi_s[i] = g_xft_im[m*1024 + i];
    }
    for (int i = tid; i < 4096; i += 256) {
        wr_s[i] = wr_g[(size_t)m*4096 + i];
        wi_s[i] = wi_g[(size_t)m*4096 + i];
    }
    __syncthreads();

    int b  = tid >> 4;
    int og = tid & 15;
    float re[4] = {0,0,0,0}, im[4] = {0,0,0,0};
    for (int c = 0; c < 64; c++) {
        float xr = xr_s[b*64 + c];
        float xi = xi_s[b*64 + c];
        float wr[4], wi[4];
        *(float4*)wr = *(const float4*)&wr_s[c*64 + 4*og];
        *(float4*)wi = *(const float4*)&wi_s[c*64 + 4*og];
        #pragma unroll
        for (int j = 0; j < 4; j++) {
            re[j] += xr*wr[j] - xi*wi[j];
            im[j] += xr*wi[j] + xi*wr[j];
        }
    }
    int base = (m*Bn + b)*Cn + 4*og;
    *(float4*)&g_oft_re[base] = make_float4(re[0], re[1], re[2], re[3]);
    *(float4*)&g_oft_im[base] = make_float4(im[0], im[1], im[2], im[3]);
}

// ---------------- K4: inverse DFT over H (scale folded) ----------------
__global__ void __launch_bounds__(128) k4_idftH() {
    __shared__ float osm[576*2];                 // [(kx*24+ky)][re,im]
    __shared__ float cs[24*128], sn[24*128];
    int bx = blockIdx.x;
    int b = bx >> 6, o = bx & 63;
    int tid = threadIdx.x;
    for (int i = tid; i < 576; i += 128) {
        osm[2*i]   = g_oft_re[i*1024 + b*64 + o];
        osm[2*i+1] = g_oft_im[i*1024 + b*64 + o];
    }
    for (int i = tid; i < 3072; i += 128) { cs[i] = g_cos[i]; sn[i] = g_sin[i]; }
    __syncthreads();

    int h = tid;
    float ar[24], ai[24];
    #pragma unroll
    for (int ky = 0; ky < 24; ky++) { ar[ky] = 0.f; ai[ky] = 0.f; }
    for (int kx = 0; kx < 24; kx++) {
        float cr = cs[kx*128 + h];
        float si = sn[kx*128 + h];
        #pragma unroll
        for (int ky = 0; ky < 24; ky++) {
            float2 ov = *(const float2*)&osm[(kx*24 + ky)*2];
            ar[ky] += ov.x*cr - ov.y*si;          // * e^{+i theta}
            ai[ky] += ov.x*si + ov.y*cr;
        }
    }
    size_t base = (((size_t)b*128 + h)*64 + o)*24;
    const float sc = 1.0f/16384.0f;               // 1/(H*W)
    #pragma unroll
    for (int ky = 0; ky < 24; ky++) {
        float s = (ky == 0) ? sc : 2.0f*sc;
        g_S_re[base + ky] = ar[ky]*s;
        g_S_im[base + ky] = ai[ky]*s;
    }
}

// ---------------- K5: fused spec-W + skip + gelu + MLP + gate -------------
__device__ __forceinline__ float gelu_f(float v) {
    return 0.5f*v*(1.0f + erff(v*0.7071067811865476f));
}

__global__ void __launch_bounds__(256) k5_final(
    const float* __restrict__ x,
    const float* __restrict__ wsk_g,
    const float* __restrict__ f1w_g, const float* __restrict__ f1b_g,
    const float* __restrict__ f2w_g, const float* __restrict__ f2b_g,
    const float* __restrict__ gate_g,
    float* __restrict__ out)
{
    extern __shared__ float sm[];
    float* xs  = sm;           // [c][w]   8192   (reused as zs in phase 3/4)
    float* h1s = sm + 8192;    // [o][w]   8192
    float* Sr  = sm + 16384;   // [o][ky]  1536
    float* Si  = sm + 17920;   // [o][ky]  1536
    float* wsk = sm + 19456;   // [o][c]   4096
    float* f1w = sm + 23552;   // [k][c]   2048
    float* f2w = sm + 25600;   // [o][k]   2048
    float* cw  = sm + 27648;   // [ky][w]  3072
    float* sw  = sm + 30720;   // [ky][w]  3072
    float* b1s = sm + 33792;   // 32
    float* b2s = sm + 33824;   // 64
    float* gs  = sm + 33888;   // 64

    int tid  = threadIdx.x;
    int lane = tid & 31;
    int wid  = tid >> 5;
    int h = blockIdx.x, b = blockIdx.y;

    // cooperative loads
    for (int i = tid; i < 2048; i += 256) {
        int c = i >> 5, w4 = i & 31;
        float4 v = *(const float4*)&x[(((size_t)b*64 + c)*128 + h)*128 + 4*w4];
        *(float4*)&xs[c*128 + 4*w4] = v;
    }
    {
        size_t sb = ((size_t)b*128 + h)*64*24;
        for (int i = tid; i < 1536; i += 256) { Sr[i] = g_S_re[sb + i]; Si[i] = g_S_im[sb + i]; }
    }
    for (int i = tid; i < 4096; i += 256) wsk[i] = wsk_g[i];
    for (int i = tid; i < 2048; i += 256) { f1w[i] = f1w_g[i]; f2w[i] = f2w_g[i]; }
    for (int i = tid; i < 3072; i += 256) { cw[i] = g_cos[i]; sw[i] = g_sin[i]; }
    if (tid < 32) b1s[tid] = f1b_g[tid];
    if (tid < 64) { b2s[tid] = f2b_g[tid]; gs[tid] = gate_g[tid]; }
    __syncthreads();

    int o0 = wid*8;
    float acc[8][4];
    #pragma unroll
    for (int oo = 0; oo < 8; oo++)
        #pragma unroll
        for (int p = 0; p < 4; p++) acc[oo][p] = 0.f;

    // phase 1: skip (x @ w_skip^T per pixel)
    for (int c = 0; c < 64; c += 4) {
        float xv[4][4];
        #pragma unroll
        for (int j = 0; j < 4; j++)
            *(float4*)xv[j] = *(const float4*)&xs[(c+j)*128 + 4*lane];
        #pragma unroll
        for (int oo = 0; oo < 8; oo++) {
            float wv[4];
            *(float4*)wv = *(const float4*)&wsk[(o0+oo)*64 + c];
            #pragma unroll
            for (int j = 0; j < 4; j++)
                #pragma unroll
                for (int p = 0; p < 4; p++)
                    acc[oo][p] += wv[j]*xv[j][p];
        }
    }

    // phase 2: spectral term (inverse DFT over W, 24 modes)
    for (int ky = 0; ky < 24; ky += 4) {
        float cv[4][4], sv[4][4];
        #pragma unroll
        for (int j = 0; j < 4; j++) {
            *(float4*)cv[j] = *(const float4*)&cw[(ky+j)*128 + 4*lane];
            *(float4*)sv[j] = *(const float4*)&sw[(ky+j)*128 + 4*lane];
        }
        #pragma unroll
        for (int oo = 0; oo < 8; oo++) {
            float srv[4], siv[4];
            *(float4*)srv = *(const float4*)&Sr[(o0+oo)*24 + ky];
            *(float4*)siv = *(const float4*)&Si[(o0+oo)*24 + ky];
            #pragma unroll
            for (int j = 0; j < 4; j++)
                #pragma unroll
                for (int p = 0; p < 4; p++)
                    acc[oo][p] += srv[j]*cv[j][p] - siv[j]*sv[j][p];
        }
    }

    // h1 = gelu(spec + skip); keep in regs + smem
    float h1r[8][4];
    #pragma unroll
    for (int oo = 0; oo < 8; oo++) {
        #pragma unroll
        for (int p = 0; p < 4; p++) h1r[oo][p] = gelu_f(acc[oo][p]);
        *(float4*)&h1s[(o0+oo)*128 + 4*lane] =
            make_float4(h1r[oo][0], h1r[oo][1], h1r[oo][2], h1r[oo][3]);
    }
    __syncthreads();

    // phase 3: fc1 + gelu  (32 hidden)
    int k0 = wid*4;
    float acc2[4][4];
    #pragma unroll
    for (int kk = 0; kk < 4; kk++)
        #pragma unroll
        for (int p = 0; p < 4; p++) acc2[kk][p] = 0.f;
    for (int c = 0; c < 64; c += 4) {
        float hv[4][4];
        #pragma unroll
        for (int j = 0; j < 4; j++)
            *(float4*)hv[j] = *(const float4*)&h1s[(c+j)*128 + 4*lane];
        #pragma unroll
        for (int kk = 0; kk < 4; kk++) {
            float wv[4];
            *(float4*)wv = *(const float4*)&f1w[(k0+kk)*64 + c];
            #pragma unroll
            for (int j = 0; j < 4; j++)
                #pragma unroll
                for (int p = 0; p < 4; p++)
                    acc2[kk][p] += wv[j]*hv[j][p];
        }
    }
    float* zs = xs;   // xs dead after phase 1; safe after the sync above
    #pragma unroll
    for (int kk = 0; kk < 4; kk++) {
        float bb = b1s[k0+kk];
        float z0 = gelu_f(acc2[kk][0] + bb);
        float z1 = gelu_f(acc2[kk][1] + bb);
        float z2 = gelu_f(acc2[kk][2] + bb);
        float z3 = gelu_f(acc2[kk][3] + bb);
        *(float4*)&zs[(k0+kk)*128 + 4*lane] = make_float4(z0, z1, z2, z3);
    }
    __syncthreads();

    // phase 4: fc2 + bias + gate*h1
    float acc3[8][4];
    #pragma unroll
    for (int oo = 0; oo < 8; oo++) {
        float bb = b2s[o0+oo];
        #pragma unroll
        for (int p = 0; p < 4; p++) acc3[oo][p] = bb;
    }
    for (int k = 0; k < 32; k += 4) {
        float zv[4][4];
        #pragma unroll
        for (int j = 0; j < 4; j++)
            *(float4*)zv[j] = *(const float4*)&zs[(k+j)*128 + 4*lane];
        #pragma unroll
        for (int oo = 0; oo < 8; oo++) {
            float wv[4];
            *(float4*)wv = *(const float4*)&f2w[(o0+oo)*32 + k];
            #pragma unroll
            for (int j = 0; j < 4; j++)
                #pragma unroll
                for (int p = 0; p < 4; p++)
                    acc3[oo][p] += wv[j]*zv[j][p];
        }
    }
    #pragma unroll
    for (int oo = 0; oo < 8; oo++) {
        float g = gs[o0+oo];
        float4 r = make_float4(acc3[oo][0] + g*h1r[oo][0],
                               acc3[oo][1] + g*h1r[oo][1],
                               acc3[oo][2] + g*h1r[oo][2],
                               acc3[oo][3] + g*h1r[oo][3]);
        *(float4*)&out[(((size_t)b*64 + (o0+oo))*128 + h)*128 + 4*lane] = r;
    }
}

// ---------------- launch ----------------
extern "C" void kernel_launch(void* const* d_in, const int* in_sizes, int n_in,
                              void* d_out, int out_size) {
    const float* x    = (const float*)d_in[0];
    const float* wre  = (const float*)d_in[1];
    const float* wim  = (const float*)d_in[2];
    const float* wsk  = (const float*)d_in[3];
    const float* f1w  = (const float*)d_in[4];
    const float* f1b  = (const float*)d_in[5];
    const float* f2w  = (const float*)d_in[6];
    const float* f2b  = (const float*)d_in[7];
    const float* gate = (const float*)d_in[8];
    float* out = (float*)d_out;

    cudaFuncSetAttribute(k5_final, cudaFuncAttributeMaxDynamicSharedMemorySize,
                         33952 * (int)sizeof(float));

    k0_init<<<6, 512>>>();
    k1_dftW<<<1024, 384>>>(x);
    k2_dftH<<<1024, 288>>>();
    k3_mix<<<576, 256>>>(wre, wim);
    k4_idftH<<<1024, 128>>>();
    dim3 g5(128, 16);
    k5_final<<<g5, 256, 33952 * sizeof(float)>>>(x, wsk, f1w, f1b, f2w, f2b, gate, out);
}

// round 2
// speedup vs baseline: 1.1002x; 1.1002x over previous
#include <cuda_runtime.h>
#include <math.h>

#define Bn 16
#define Cn 64
#define Hn 128
#define Wn 128
#define MXn 24
#define MYn 24
#define HIDn 32

// ---------------- scratch (device globals; no runtime allocation) ----------
__device__ float g_xw_re[Bn*Cn*Hn*MYn];       // [b][c][h][ky]
__device__ float g_xw_im[Bn*Cn*Hn*MYn];
__device__ float g_xft_re[MXn*MYn*Bn*Cn];     // [(kx*24+ky)][b][c]
__device__ float g_xft_im[MXn*MYn*Bn*Cn];
__device__ float g_oft_re[MXn*MYn*Bn*Cn];     // [(kx*24+ky)][b][o]
__device__ float g_oft_im[MXn*MYn*Bn*Cn];
__device__ float g_S_re[Bn*Hn*Cn*MYn];        // [b][h][o][ky]  (scaled)
__device__ float g_S_im[Bn*Hn*Cn*MYn];
__device__ float g_cos[MYn*Wn];               // cos(2*pi*k*w/128)
__device__ float g_sin[MYn*Wn];               // sin(2*pi*k*w/128)
__device__ float g_twT[Wn*48];                // [w][j] j<24: cos, j>=24: -sin

// ---------------- packed f32x2 helpers ----------------
__device__ __forceinline__ float2 ffma2(float2 a, float2 b, float2 c) {
    float2 r;
    asm("fma.rn.f32x2 %0, %1, %2, %3;"
        : "=l"(reinterpret_cast<unsigned long long&>(r))
        : "l"(reinterpret_cast<unsigned long long&>(a)),
          "l"(reinterpret_cast<unsigned long long&>(b)),
          "l"(reinterpret_cast<unsigned long long&>(c)));
    return r;
}
__device__ __forceinline__ float2 dup2(float x) { return make_float2(x, x); }

__device__ __forceinline__ float gelu_f(float v) {
    return 0.5f*v*(1.0f + erff(v*0.7071067811865476f));
}

// ---------------- K0: twiddle init ----------------
__global__ void k0_init() {
    int i = blockIdx.x*blockDim.x + threadIdx.x;
    if (i >= MYn*Wn) return;
    int k = i / Wn, w = i % Wn;
    float s, c;
    sincospif((float)(k*w) / 64.0f, &s, &c);
    g_cos[k*Wn + w] = c;
    g_sin[k*Wn + w] = s;
    g_twT[w*48 + k]      = c;
    g_twT[w*48 + 24 + k] = -s;
}

// ---------------- K1: partial DFT over W ----------------
__global__ void __launch_bounds__(384) k1_dftW(const float* __restrict__ x) {
    __shared__ float Xs[32*132];
    __shared__ float Tw[32*48];
    int tid = threadIdx.x;
    int rg = tid & 31;
    int jg = tid >> 5;
    int row0 = blockIdx.x * 128;

    float acc[4][4];
    #pragma unroll
    for (int i = 0; i < 4; i++)
        #pragma unroll
        for (int j = 0; j < 4; j++) acc[i][j] = 0.f;

    for (int kt = 0; kt < 4; kt++) {
        for (int i = tid; i < 4096; i += 384) {
            int r = i >> 5, w = i & 31;
            Xs[w*132 + r] = x[(size_t)(row0 + r)*128 + kt*32 + w];
        }
        for (int i = tid; i < 32*48; i += 384)
            Tw[i] = g_twT[kt*32*48 + i];
        __syncthreads();
        #pragma unroll
        for (int kk = 0; kk < 32; kk++) {
            float xv[4], tv[4];
            *(float4*)xv = *(const float4*)&Xs[kk*132 + 4*rg];
            *(float4*)tv = *(const float4*)&Tw[kk*48 + 4*jg];
            #pragma unroll
            for (int i = 0; i < 4; i++)
                #pragma unroll
                for (int j = 0; j < 4; j++)
                    acc[i][j] += xv[i]*tv[j];
        }
        __syncthreads();
    }

    float* dst = (jg < 6) ? g_xw_re : g_xw_im;
    int col = (jg < 6) ? (4*jg) : (4*jg - 24);
    #pragma unroll
    for (int i = 0; i < 4; i++) {
        int r = row0 + 4*rg + i;
        *(float4*)&dst[(size_t)r*24 + col] =
            make_float4(acc[i][0], acc[i][1], acc[i][2], acc[i][3]);
    }
}

// ---------------- K2: partial DFT over H ----------------
__global__ void __launch_bounds__(288) k2_dftH() {
    __shared__ float xr[128*24], xi[128*24];
    __shared__ float cs[24*128], sn[24*128];
    int bc = blockIdx.x;
    int tid = threadIdx.x;
    size_t base = (size_t)bc * (128*24);
    for (int i = tid; i < 3072; i += 288) {
        xr[i] = g_xw_re[base + i];
        xi[i] = g_xw_im[base + i];
        cs[i] = g_cos[i];
        sn[i] = g_sin[i];
    }
    __syncthreads();

    int ky  = tid % 24;
    int kxg = tid / 24;
    int kx0 = 2*kxg, kx1 = 2*kxg + 1;
    float re0 = 0.f, im0 = 0.f, re1 = 0.f, im1 = 0.f;
    for (int h = 0; h < 128; h++) {
        float a = xr[h*24 + ky];
        float b = xi[h*24 + ky];
        float c0 = cs[kx0*128 + h], s0 = sn[kx0*128 + h];
        float c1 = cs[kx1*128 + h], s1 = sn[kx1*128 + h];
        re0 += a*c0 + b*s0;  im0 += b*c0 - a*s0;
        re1 += a*c1 + b*s1;  im1 += b*c1 - a*s1;
    }
    int b = bc >> 6, c = bc & 63;
    int m0 = kx0*24 + ky, m1 = kx1*24 + ky;
    g_xft_re[(m0*Bn + b)*Cn + c] = re0;
    g_xft_im[(m0*Bn + b)*Cn + c] = im0;
    g_xft_re[(m1*Bn + b)*Cn + c] = re1;
    g_xft_im[(m1*Bn + b)*Cn + c] = im1;
}

// ---------------- K3: per-mode complex channel mix (512 thr) --------------
__global__ void __launch_bounds__(512) k3_mix(const float* __restrict__ wr_g,
                                              const float* __restrict__ wi_g) {
    __shared__ float xr_s[1024], xi_s[1024];
    __shared__ float wr_s[4096], wi_s[4096];
    int m = blockIdx.x, tid = threadIdx.x;
    for (int i = tid; i < 1024; i += 512) {
        xr_s[i] = g_xft_re[m*1024 + i];
        xi_s[i] = g_xft_im[m*1024 + i];
    }
    for (int i = tid; i < 4096; i += 512) {
        wr_s[i] = wr_g[(size_t)m*4096 + i];
        wi_s[i] = wi_g[(size_t)m*4096 + i];
    }
    __syncthreads();

    int b  = tid >> 5;      // 0..15
    int og = tid & 31;      // 2 outputs each
    float2 re = make_float2(0.f, 0.f), im = make_float2(0.f, 0.f);
    #pragma unroll 4
    for (int c = 0; c < 64; c++) {
        float xr = xr_s[b*64 + c];
        float xi = xi_s[b*64 + c];
        float2 wr = *(const float2*)&wr_s[c*64 + 2*og];
        float2 wi = *(const float2*)&wi_s[c*64 + 2*og];
        re = ffma2(dup2(xr),  wr, re);
        re = ffma2(dup2(-xi), wi, re);
        im = ffma2(dup2(xr),  wi, im);
        im = ffma2(dup2(xi),  wr, im);
    }
    int base = (m*Bn + b)*Cn + 2*og;
    *(float2*)&g_oft_re[base] = re;
    *(float2*)&g_oft_im[base] = im;
}

// ---------------- K4: inverse DFT over H (scale folded) ----------------
__global__ void __launch_bounds__(128) k4_idftH() {
    __shared__ float osm[576*2];
    __shared__ float cs[24*128], sn[24*128];
    int bx = blockIdx.x;
    int b = bx >> 6, o = bx & 63;
    int tid = threadIdx.x;
    for (int i = tid; i < 576; i += 128) {
        osm[2*i]   = g_oft_re[i*1024 + b*64 + o];
        osm[2*i+1] = g_oft_im[i*1024 + b*64 + o];
    }
    for (int i = tid; i < 3072; i += 128) { cs[i] = g_cos[i]; sn[i] = g_sin[i]; }
    __syncthreads();

    int h = tid;
    float ar[24], ai[24];
    #pragma unroll
    for (int ky = 0; ky < 24; ky++) { ar[ky] = 0.f; ai[ky] = 0.f; }
    for (int kx = 0; kx < 24; kx++) {
        float cr = cs[kx*128 + h];
        float si = sn[kx*128 + h];
        #pragma unroll
        for (int ky = 0; ky < 24; ky++) {
            float2 ov = *(const float2*)&osm[(kx*24 + ky)*2];
            ar[ky] += ov.x*cr - ov.y*si;
            ai[ky] += ov.x*si + ov.y*cr;
        }
    }
    size_t base = (((size_t)b*128 + h)*64 + o)*24;
    const float sc = 1.0f/16384.0f;
    #pragma unroll
    for (int ky = 0; ky < 24; ky++) {
        float s = (ky == 0) ? sc : 2.0f*sc;
        g_S_re[base + ky] = ar[ky]*s;
        g_S_im[base + ky] = ai[ky]*s;
    }
}

// ---------------- K5: fused final — 2 h-rows/block, f32x2 math ------------
// smem float offsets:
#define OFF_XS    0        // [hr][c][128]     16384  (reused as zs: [hr][k][128])
#define OFF_H1S   16384    // [hr][o][128]     16384
#define OFF_SRT   32768    // [hr][ky][68]      3264
#define OFF_SIT   36032    //                   3264  (stores -Si)
#define OFF_WSKT  39296    // [c][68]           4352
#define OFF_F1WT  43648    // [c][36]           2304
#define OFF_F2WT  45952    // [k][68]           2176
#define OFF_CW    48128    // [ky][128]         3072
#define OFF_SW    51200    //                   3072
#define OFF_B1    54272    // 32
#define OFF_B2    54304    // 64
#define OFF_GS    54368    // 64
#define SMEM_K5_FLOATS 54432

__global__ void __launch_bounds__(256) k5_final(
    const float* __restrict__ x,
    const float* __restrict__ wsk_g,
    const float* __restrict__ f1w_g, const float* __restrict__ f1b_g,
    const float* __restrict__ f2w_g, const float* __restrict__ f2b_g,
    const float* __restrict__ gate_g,
    float* __restrict__ out)
{
    extern __shared__ float sm[];
    float* xs   = sm + OFF_XS;
    float* h1s  = sm + OFF_H1S;
    float* SrT  = sm + OFF_SRT;
    float* SiT  = sm + OFF_SIT;
    float* wskT = sm + OFF_WSKT;
    float* f1wT = sm + OFF_F1WT;
    float* f2wT = sm + OFF_F2WT;
    float* cw   = sm + OFF_CW;
    float* sw   = sm + OFF_SW;
    float* b1s  = sm + OFF_B1;
    float* b2s  = sm + OFF_B2;
    float* gs   = sm + OFF_GS;

    int tid  = threadIdx.x;
    int lane = tid & 31;
    int wid  = tid >> 5;
    int hb = blockIdx.x;          // 0..63 -> rows 2*hb, 2*hb+1
    int b  = blockIdx.y;

    int wg = lane & 15;
    int hr = lane >> 4;
    int w0 = wg * 8;
    int o0 = wid * 8;

    // ---- cooperative loads ----
    // x -> xs[hr][c][w]
    for (int i = tid; i < 4096; i += 256) {
        int f = i * 4;
        int xhr = f >> 13, c = (f >> 7) & 63, w = f & 127;
        *(float4*)&xs[f] =
            *(const float4*)&x[(((size_t)b*64 + c)*128 + (2*hb + xhr))*128 + w];
    }
    // S -> transposed, padded; SiT holds -S_im
    {
        size_t sb0 = ((size_t)b*128 + 2*hb) * (64*24);
        for (int i = tid; i < 3072; i += 256) {
            int shr = i / 1536, j = i - shr*1536;
            int o = j / 24, ky = j - o*24;
            int d = (shr*24 + ky)*68 + o;
            SrT[d] =  g_S_re[sb0 + (size_t)shr*1536 + j];
            SiT[d] = -g_S_im[sb0 + (size_t)shr*1536 + j];
        }
    }
    // wsk [o][c] -> wskT[c][68]
    for (int i = tid; i < 4096; i += 256) {
        int o = i >> 6, c = i & 63;
        wskT[c*68 + o] = wsk_g[i];
    }
    // f1w [k][c] -> f1wT[c][36]
    for (int i = tid; i < 2048; i += 256) {
        int k = i >> 6, c = i & 63;
        f1wT[c*36 + k] = f1w_g[i];
    }
    // f2w [o][k] -> f2wT[k][68]
    for (int i = tid; i < 2048; i += 256) {
        int o = i >> 5, k = i & 31;
        f2wT[k*68 + o] = f2w_g[i];
    }
    for (int i = tid; i < 3072; i += 256) { cw[i] = g_cos[i]; sw[i] = g_sin[i]; }
    if (tid < 32) b1s[tid] = f1b_g[tid];
    if (tid < 64) { b2s[tid] = f2b_g[tid]; gs[tid] = gate_g[tid]; }
    __syncthreads();

    // ---- phase 1+2: spec + skip -> gelu -> h1 ----
    float2 acc[8][4];
    #pragma unroll
    for (int oo = 0; oo < 8; oo++)
        #pragma unroll
        for (int p = 0; p < 4; p++) acc[oo][p] = make_float2(0.f, 0.f);

    const float* xrow = xs + hr*8192;
    #pragma unroll 2
    for (int c = 0; c < 64; c++) {
        float4 xa = *(const float4*)&xrow[c*128 + w0];
        float4 xb = *(const float4*)&xrow[c*128 + w0 + 4];
        float2 xv[4] = { make_float2(xa.x,xa.y), make_float2(xa.z,xa.w),
                         make_float2(xb.x,xb.y), make_float2(xb.z,xb.w) };
        float4 wa = *(const float4*)&wskT[c*68 + o0];
        float4 wb = *(const float4*)&wskT[c*68 + o0 + 4];
        float wv[8] = { wa.x, wa.y, wa.z, wa.w, wb.x, wb.y, wb.z, wb.w };
        #pragma unroll
        for (int oo = 0; oo < 8; oo++) {
            float2 wd = dup2(wv[oo]);
            #pragma unroll
            for (int p = 0; p < 4; p++) acc[oo][p] = ffma2(wd, xv[p], acc[oo][p]);
        }
    }

    #pragma unroll 2
    for (int ky = 0; ky < 24; ky++) {
        float4 ca = *(const float4*)&cw[ky*128 + w0];
        float4 cb = *(const float4*)&cw[ky*128 + w0 + 4];
        float4 sa = *(const float4*)&sw[ky*128 + w0];
        float4 sb = *(const float4*)&sw[ky*128 + w0 + 4];
        float2 cv[4] = { make_float2(ca.x,ca.y), make_float2(ca.z,ca.w),
                         make_float2(cb.x,cb.y), make_float2(cb.z,cb.w) };
        float2 sv[4] = { make_float2(sa.x,sa.y), make_float2(sa.z,sa.w),
                         make_float2(sb.x,sb.y), make_float2(sb.z,sb.w) };
        int sbase = (hr*24 + ky)*68 + o0;
        float4 ra = *(const float4*)&SrT[sbase];
        float4 rb = *(const float4*)&SrT[sbase + 4];
        float4 ia = *(const float4*)&SiT[sbase];
        float4 ib = *(const float4*)&SiT[sbase + 4];
        float rv[8] = { ra.x, ra.y, ra.z, ra.w, rb.x, rb.y, rb.z, rb.w };
        float iv[8] = { ia.x, ia.y, ia.z, ia.w, ib.x, ib.y, ib.z, ib.w };
        #pragma unroll
        for (int oo = 0; oo < 8; oo++) {
            float2 rd = dup2(rv[oo]);
            float2 id = dup2(iv[oo]);   // already negated
            #pragma unroll
            for (int p = 0; p < 4; p++) {
                acc[oo][p] = ffma2(rd, cv[p], acc[oo][p]);
                acc[oo][p] = ffma2(id, sv[p], acc[oo][p]);
            }
        }
    }

    #pragma unroll
    for (int oo = 0; oo < 8; oo++) {
        float h[8];
        #pragma unroll
        for (int p = 0; p < 4; p++) {
            h[2*p]   = gelu_f(acc[oo][p].x);
            h[2*p+1] = gelu_f(acc[oo][p].y);
        }
        float* d = &h1s[hr*8192 + (o0+oo)*128 + w0];
        *(float4*)d       = make_float4(h[0], h[1], h[2], h[3]);
        *(float4*)(d + 4) = make_float4(h[4], h[5], h[6], h[7]);
    }
    __syncthreads();

    // ---- phase 3: fc1 + gelu -> zs (= xs region) ----
    int k0 = wid * 4;
    float2 acc2[4][4];
    #pragma unroll
    for (int kk = 0; kk < 4; kk++)
        #pragma unroll
        for (int p = 0; p < 4; p++) acc2[kk][p] = make_float2(0.f, 0.f);

    const float* h1row = h1s + hr*8192;
    #pragma unroll 2
    for (int c = 0; c < 64; c++) {
        float4 ha = *(const float4*)&h1row[c*128 + w0];
        float4 hb2 = *(const float4*)&h1row[c*128 + w0 + 4];
        float2 hv[4] = { make_float2(ha.x,ha.y), make_float2(ha.z,ha.w),
                         make_float2(hb2.x,hb2.y), make_float2(hb2.z,hb2.w) };
        float4 fv = *(const float4*)&f1wT[c*36 + k0];
        float fw[4] = { fv.x, fv.y, fv.z, fv.w };
        #pragma unroll
        for (int kk = 0; kk < 4; kk++) {
            float2 fd = dup2(fw[kk]);
            #pragma unroll
            for (int p = 0; p < 4; p++) acc2[kk][p] = ffma2(fd, hv[p], acc2[kk][p]);
        }
    }
    float* zs = xs;   // xs dead after phase 1
    #pragma unroll
    for (int kk = 0; kk < 4; kk++) {
        float bb = b1s[k0+kk];
        float z[8];
        #pragma unroll
        for (int p = 0; p < 4; p++) {
            z[2*p]   = gelu_f(acc2[kk][p].x + bb);
            z[2*p+1] = gelu_f(acc2[kk][p].y + bb);
        }
        float* d = &zs[hr*4096 + (k0+kk)*128 + w0];
        *(float4*)d       = make_float4(z[0], z[1], z[2], z[3]);
        *(float4*)(d + 4) = make_float4(z[4], z[5], z[6], z[7]);
    }
    __syncthreads();

    // ---- phase 4: fc2 + bias + gate*h1 ----
    float2 acc3[8][4];
    #pragma unroll
    for (int oo = 0; oo < 8; oo++) {
        float bb = b2s[o0+oo];
        #pragma unroll
        for (int p = 0; p < 4; p++) acc3[oo][p] = make_float2(bb, bb);
    }
    const float* zrow = zs + hr*4096;
    #pragma unroll 2
    for (int k = 0; k < 32; k++) {
        float4 za = *(const float4*)&zrow[k*128 + w0];
        float4 zb = *(const float4*)&zrow[k*128 + w0 + 4];
        float2 zv[4] = { make_float2(za.x,za.y), make_float2(za.z,za.w),
                         make_float2(zb.x,zb.y), make_float2(zb.z,zb.w) };
        float4 fa = *(const float4*)&f2wT[k*68 + o0];
        float4 fb = *(const float4*)&f2wT[k*68 + o0 + 4];
        float fw[8] = { fa.x, fa.y, fa.z, fa.w, fb.x, fb.y, fb.z, fb.w };
        #pragma unroll
        for (int oo = 0; oo < 8; oo++) {
            float2 fd = dup2(fw[oo]);
            #pragma unroll
            for (int p = 0; p < 4; p++) acc3[oo][p] = ffma2(fd, zv[p], acc3[oo][p]);
        }
    }
    #pragma unroll
    for (int oo = 0; oo < 8; oo++) {
        float g = gs[o0+oo];
        const float* hsrc = &h1s[hr*8192 + (o0+oo)*128 + w0];
        float4 h1a = *(const float4*)hsrc;
        float4 h1b = *(const float4*)(hsrc + 4);
        float4 r0 = make_float4(acc3[oo][0].x + g*h1a.x, acc3[oo][0].y + g*h1a.y,
                                acc3[oo][1].x + g*h1a.z, acc3[oo][1].y + g*h1a.w);
        float4 r1 = make_float4(acc3[oo][2].x + g*h1b.x, acc3[oo][2].y + g*h1b.y,
                                acc3[oo][3].x + g*h1b.z, acc3[oo][3].y + g*h1b.w);
        float* dst = &out[(((size_t)b*64 + (o0+oo))*128 + (2*hb + hr))*128 + w0];
        *(float4*)dst       = r0;
        *(float4*)(dst + 4) = r1;
    }
}

// ---------------- launch ----------------
extern "C" void kernel_launch(void* const* d_in, const int* in_sizes, int n_in,
                              void* d_out, int out_size) {
    const float* x    = (const float*)d_in[0];
    const float* wre  = (const float*)d_in[1];
    const float* wim  = (const float*)d_in[2];
    const float* wsk  = (const float*)d_in[3];
    const float* f1w  = (const float*)d_in[4];
    const float* f1b  = (const float*)d_in[5];
    const float* f2w  = (const float*)d_in[6];
    const float* f2b  = (const float*)d_in[7];
    const float* gate = (const float*)d_in[8];
    float* out = (float*)d_out;

    static int configured = 0;
    if (!configured) {
        cudaFuncSetAttribute(k5_final, cudaFuncAttributeMaxDynamicSharedMemorySize,
                             SMEM_K5_FLOATS * (int)sizeof(float));
        configured = 1;
    }

    k0_init<<<6, 512>>>();
    k1_dftW<<<1024, 384>>>(x);
    k2_dftH<<<1024, 288>>>();
    k3_mix<<<576, 512>>>(wre, wim);
    k4_idftH<<<1024, 128>>>();
    dim3 g5(64, 16);
    k5_final<<<g5, 256, SMEM_K5_FLOATS * sizeof(float)>>>(
        x, wsk, f1w, f1b, f2w, f2b, gate, out);
}

// round 3
// speedup vs baseline: 1.3699x; 1.2452x over previous
#include <cuda_runtime.h>
#include <math.h>

#define Bn 16
#define Cn 64
#define Hn 128
#define Wn 128
#define MXn 24
#define MYn 24
#define HIDn 32

// ---------------- scratch (device globals; no runtime allocation) ----------
__device__ float g_xw_re[Bn*Cn*Hn*MYn];       // [b][c][h][ky]
__device__ float g_xw_im[Bn*Cn*Hn*MYn];
__device__ float g_xft_re[MXn*MYn*Bn*Cn];     // [(kx*24+ky)][b][c]
__device__ float g_xft_im[MXn*MYn*Bn*Cn];
__device__ float g_oft_re[MXn*MYn*Bn*Cn];     // [(kx*24+ky)][b][o]
__device__ float g_oft_im[MXn*MYn*Bn*Cn];
__device__ float g_S_re[Bn*Hn*Cn*MYn];        // [b][h][o][ky]  (scaled)
__device__ float g_S_im[Bn*Hn*Cn*MYn];
__device__ float g_cos[MYn*Wn];               // cos(2*pi*k*w/128)
__device__ float g_sin[MYn*Wn];               // sin(2*pi*k*w/128)
__device__ float g_twT[Wn*48];                // [w][j] j<24: cos, j>=24: -sin

// ---------------- packed f32x2 helpers ----------------
__device__ __forceinline__ float2 ffma2(float2 a, float2 b, float2 c) {
    float2 r;
    asm("fma.rn.f32x2 %0, %1, %2, %3;"
        : "=l"(reinterpret_cast<unsigned long long&>(r))
        : "l"(reinterpret_cast<unsigned long long&>(a)),
          "l"(reinterpret_cast<unsigned long long&>(b)),
          "l"(reinterpret_cast<unsigned long long&>(c)));
    return r;
}
__device__ __forceinline__ float2 dup2(float x) { return make_float2(x, x); }

__device__ __forceinline__ float gelu_f(float v) {
    return 0.5f*v*(1.0f + erff(v*0.7071067811865476f));
}

// ---------------- K0: twiddle init ----------------
__global__ void k0_init() {
    int i = blockIdx.x*blockDim.x + threadIdx.x;
    if (i >= MYn*Wn) return;
    int k = i / Wn, w = i % Wn;
    float s, c;
    sincospif((float)(k*w) / 64.0f, &s, &c);
    g_cos[k*Wn + w] = c;
    g_sin[k*Wn + w] = s;
    g_twT[w*48 + k]      = c;
    g_twT[w*48 + 24 + k] = -s;
}

// ---------------- K1: partial DFT over W (ffma2 on row pairs) -------------
__global__ void __launch_bounds__(384) k1_dftW(const float* __restrict__ x) {
    __shared__ float Xs[32*132];
    __shared__ float Tw[32*48];
    int tid = threadIdx.x;
    int rg = tid & 31;
    int jg = tid >> 5;
    int row0 = blockIdx.x * 128;

    float2 acc[2][4];   // [row pair][j]
    #pragma unroll
    for (int i = 0; i < 2; i++)
        #pragma unroll
        for (int j = 0; j < 4; j++) acc[i][j] = make_float2(0.f, 0.f);

    for (int kt = 0; kt < 4; kt++) {
        for (int i = tid; i < 4096; i += 384) {
            int r = i >> 5, w = i & 31;
            Xs[w*132 + r] = x[(size_t)(row0 + r)*128 + kt*32 + w];
        }
        for (int i = tid; i < 32*48; i += 384)
            Tw[i] = g_twT[kt*32*48 + i];
        __syncthreads();
        #pragma unroll
        for (int kk = 0; kk < 32; kk++) {
            float4 xa = *(const float4*)&Xs[kk*132 + 4*rg];
            float2 xp0 = make_float2(xa.x, xa.y);
            float2 xp1 = make_float2(xa.z, xa.w);
            float4 tq = *(const float4*)&Tw[kk*48 + 4*jg];
            float tv[4] = { tq.x, tq.y, tq.z, tq.w };
            #pragma unroll
            for (int j = 0; j < 4; j++) {
                float2 td = dup2(tv[j]);
                acc[0][j] = ffma2(xp0, td, acc[0][j]);
                acc[1][j] = ffma2(xp1, td, acc[1][j]);
            }
        }
        __syncthreads();
    }

    float* dst = (jg < 6) ? g_xw_re : g_xw_im;
    int col = (jg < 6) ? (4*jg) : (4*jg - 24);
    // rows: 4*rg + {0,1} from acc[0] (x,y), 4*rg + {2,3} from acc[1] (x,y)
    #pragma unroll
    for (int i = 0; i < 4; i++) {
        int pair = i >> 1, half = i & 1;
        float v0 = half ? acc[pair][0].y : acc[pair][0].x;
        float v1 = half ? acc[pair][1].y : acc[pair][1].x;
        float v2 = half ? acc[pair][2].y : acc[pair][2].x;
        float v3 = half ? acc[pair][3].y : acc[pair][3].x;
        int r = row0 + 4*rg + i;
        *(float4*)&dst[(size_t)r*24 + col] = make_float4(v0, v1, v2, v3);
    }
}

// ---------------- K2: partial DFT over H (ffma2 on re/im) -----------------
__global__ void __launch_bounds__(288) k2_dftH() {
    __shared__ float xr[128*24], xi[128*24];
    __shared__ float cs[24*128], sn[24*128];
    int bc = blockIdx.x;
    int tid = threadIdx.x;
    size_t base = (size_t)bc * (128*24);
    for (int i = tid; i < 3072; i += 288) {
        xr[i] = g_xw_re[base + i];
        xi[i] = g_xw_im[base + i];
        cs[i] = g_cos[i];
        sn[i] = g_sin[i];
    }
    __syncthreads();

    int ky  = tid % 24;
    int kxg = tid / 24;
    int kx0 = 2*kxg, kx1 = 2*kxg + 1;
    float2 acc0 = make_float2(0.f, 0.f);   // (re0, im0)
    float2 acc1 = make_float2(0.f, 0.f);   // (re1, im1)
    #pragma unroll 4
    for (int h = 0; h < 128; h++) {
        float a = xr[h*24 + ky];
        float b = xi[h*24 + ky];
        float2 ab  = make_float2(a, b);
        float2 bna = make_float2(b, -a);
        acc0 = ffma2(ab,  dup2(cs[kx0*128 + h]), acc0);
        acc0 = ffma2(bna, dup2(sn[kx0*128 + h]), acc0);
        acc1 = ffma2(ab,  dup2(cs[kx1*128 + h]), acc1);
        acc1 = ffma2(bna, dup2(sn[kx1*128 + h]), acc1);
    }
    int b = bc >> 6, c = bc & 63;
    int m0 = kx0*24 + ky, m1 = kx1*24 + ky;
    g_xft_re[(m0*Bn + b)*Cn + c] = acc0.x;
    g_xft_im[(m0*Bn + b)*Cn + c] = acc0.y;
    g_xft_re[(m1*Bn + b)*Cn + c] = acc1.x;
    g_xft_im[(m1*Bn + b)*Cn + c] = acc1.y;
}

// ---------------- K3: per-mode complex channel mix (512 thr) --------------
__global__ void __launch_bounds__(512) k3_mix(const float* __restrict__ wr_g,
                                              const float* __restrict__ wi_g) {
    __shared__ float xr_s[1024], xi_s[1024];
    __shared__ float wr_s[4096], wi_s[4096];
    int m = blockIdx.x, tid = threadIdx.x;
    for (int i = tid; i < 1024; i += 512) {
        xr_s[i] = g_xft_re[m*1024 + i];
        xi_s[i] = g_xft_im[m*1024 + i];
    }
    for (int i = tid; i < 4096; i += 512) {
        wr_s[i] = wr_g[(size_t)m*4096 + i];
        wi_s[i] = wi_g[(size_t)m*4096 + i];
    }
    __syncthreads();

    int b  = tid >> 5;      // 0..15
    int og = tid & 31;      // 2 outputs each
    float2 re = make_float2(0.f, 0.f), im = make_float2(0.f, 0.f);
    #pragma unroll 4
    for (int c = 0; c < 64; c++) {
        float xr = xr_s[b*64 + c];
        float xi = xi_s[b*64 + c];
        float2 wr = *(const float2*)&wr_s[c*64 + 2*og];
        float2 wi = *(const float2*)&wi_s[c*64 + 2*og];
        re = ffma2(dup2(xr),  wr, re);
        re = ffma2(dup2(-xi), wi, re);
        im = ffma2(dup2(xr),  wi, im);
        im = ffma2(dup2(xi),  wr, im);
    }
    int base = (m*Bn + b)*Cn + 2*og;
    *(float2*)&g_oft_re[base] = re;
    *(float2*)&g_oft_im[base] = im;
}

// ---------------- K4: inverse DFT over H (ffma2 on ar/ai) -----------------
__global__ void __launch_bounds__(128) k4_idftH() {
    __shared__ float osm[576*2];
    __shared__ float cs[24*128], sn[24*128];
    int bx = blockIdx.x;
    int b = bx >> 6, o = bx & 63;
    int tid = threadIdx.x;
    for (int i = tid; i < 576; i += 128) {
        osm[2*i]   = g_oft_re[i*1024 + b*64 + o];
        osm[2*i+1] = g_oft_im[i*1024 + b*64 + o];
    }
    for (int i = tid; i < 3072; i += 128) { cs[i] = g_cos[i]; sn[i] = g_sin[i]; }
    __syncthreads();

    int h = tid;
    float2 acc[24];   // (ar, ai)
    #pragma unroll
    for (int ky = 0; ky < 24; ky++) acc[ky] = make_float2(0.f, 0.f);
    #pragma unroll 2
    for (int kx = 0; kx < 24; kx++) {
        float cr = cs[kx*128 + h];
        float si = sn[kx*128 + h];
        float2 v1 = make_float2(cr, si);
        float2 v2 = make_float2(-si, cr);
        #pragma unroll
        for (int ky = 0; ky < 24; ky++) {
            float2 ov = *(const float2*)&osm[(kx*24 + ky)*2];
            acc[ky] = ffma2(dup2(ov.x), v1, acc[ky]);
            acc[ky] = ffma2(dup2(ov.y), v2, acc[ky]);
        }
    }
    size_t base = (((size_t)b*128 + h)*64 + o)*24;
    const float sc = 1.0f/16384.0f;
    #pragma unroll
    for (int ky = 0; ky < 24; ky++) {
        float s = (ky == 0) ? sc : 2.0f*sc;
        g_S_re[base + ky] = acc[ky].x*s;
        g_S_im[base + ky] = acc[ky].y*s;
    }
}

// ---------------- K5: fused final — 2 rows, 512 threads, f32x2 ------------
#define OFF_XS    0        // [hr][c][128]     16384  (reused as zs)
#define OFF_H1S   16384    // [hr][o][128]     16384
#define OFF_SRT   32768    // [hr][ky][68]      3264
#define OFF_SIT   36032    //                   3264  (stores -Si)
#define OFF_WSKT  39296    // [c][68]           4352
#define OFF_F1WT  43648    // [c][36]           2304
#define OFF_F2WT  45952    // [k][68]           2176
#define OFF_CW    48128    // [ky][128]         3072
#define OFF_SW    51200    //                   3072
#define OFF_B1    54272    // 32
#define OFF_B2    54304    // 64
#define OFF_GS    54368    // 64
#define SMEM_K5_FLOATS 54432

__global__ void __launch_bounds__(512, 1) k5_final(
    const float* __restrict__ x,
    const float* __restrict__ wsk_g,
    const float* __restrict__ f1w_g, const float* __restrict__ f1b_g,
    const float* __restrict__ f2w_g, const float* __restrict__ f2b_g,
    const float* __restrict__ gate_g,
    float* __restrict__ out)
{
    extern __shared__ float sm[];
    float* xs   = sm + OFF_XS;
    float* h1s  = sm + OFF_H1S;
    float* SrT  = sm + OFF_SRT;
    float* SiT  = sm + OFF_SIT;
    float* wskT = sm + OFF_WSKT;
    float* f1wT = sm + OFF_F1WT;
    float* f2wT = sm + OFF_F2WT;
    float* cw   = sm + OFF_CW;
    float* sw   = sm + OFF_SW;
    float* b1s  = sm + OFF_B1;
    float* b2s  = sm + OFF_B2;
    float* gs   = sm + OFF_GS;

    int tid  = threadIdx.x;
    int lane = tid & 31;
    int wid  = tid >> 5;          // 0..15
    int hr   = wid >> 3;          // 0,1: row within block
    int ow   = wid & 7;           // o group
    int o0   = ow * 8;
    int w0   = lane * 4;
    int hb = blockIdx.x;          // rows 2*hb, 2*hb+1
    int b  = blockIdx.y;

    // ---- cooperative loads ----
    for (int i = tid; i < 4096; i += 512) {
        int f = i * 4;
        int xhr = f >> 13, c = (f >> 7) & 63, w = f & 127;
        *(float4*)&xs[f] =
            *(const float4*)&x[(((size_t)b*64 + c)*128 + (2*hb + xhr))*128 + w];
    }
    {
        size_t sb0 = ((size_t)b*128 + 2*hb) * (64*24);
        for (int i = tid; i < 3072; i += 512) {
            int shr = i / 1536, j = i - shr*1536;
            int o = j / 24, ky = j - o*24;
            int d = (shr*24 + ky)*68 + o;
            SrT[d] =  g_S_re[sb0 + (size_t)shr*1536 + j];
            SiT[d] = -g_S_im[sb0 + (size_t)shr*1536 + j];
        }
    }
    for (int i = tid; i < 4096; i += 512) {
        int o = i >> 6, c = i & 63;
        wskT[c*68 + o] = wsk_g[i];
    }
    for (int i = tid; i < 2048; i += 512) {
        int k = i >> 6, c = i & 63;
        f1wT[c*36 + k] = f1w_g[i];
    }
    for (int i = tid; i < 2048; i += 512) {
        int o = i >> 5, k = i & 31;
        f2wT[k*68 + o] = f2w_g[i];
    }
    for (int i = tid; i < 3072; i += 512) { cw[i] = g_cos[i]; sw[i] = g_sin[i]; }
    if (tid < 32) b1s[tid] = f1b_g[tid];
    if (tid < 64) { b2s[tid] = f2b_g[tid]; gs[tid] = gate_g[tid]; }
    __syncthreads();

    // ---- phase 1: skip ----
    float2 acc[8][2];
    #pragma unroll
    for (int oo = 0; oo < 8; oo++)
        #pragma unroll
        for (int p = 0; p < 2; p++) acc[oo][p] = make_float2(0.f, 0.f);

    const float* xrow = xs + hr*8192;
    #pragma unroll 2
    for (int c = 0; c < 64; c++) {
        float4 xa = *(const float4*)&xrow[c*128 + w0];
        float2 xv[2] = { make_float2(xa.x,xa.y), make_float2(xa.z,xa.w) };
        float4 wa = *(const float4*)&wskT[c*68 + o0];
        float4 wb = *(const float4*)&wskT[c*68 + o0 + 4];
        float wv[8] = { wa.x, wa.y, wa.z, wa.w, wb.x, wb.y, wb.z, wb.w };
        #pragma unroll
        for (int oo = 0; oo < 8; oo++) {
            float2 wd = dup2(wv[oo]);
            acc[oo][0] = ffma2(wd, xv[0], acc[oo][0]);
            acc[oo][1] = ffma2(wd, xv[1], acc[oo][1]);
        }
    }

    // ---- phase 2: spectral (inverse DFT over W) ----
    #pragma unroll 2
    for (int ky = 0; ky < 24; ky++) {
        float4 ca = *(const float4*)&cw[ky*128 + w0];
        float4 sa = *(const float4*)&sw[ky*128 + w0];
        float2 cv[2] = { make_float2(ca.x,ca.y), make_float2(ca.z,ca.w) };
        float2 sv[2] = { make_float2(sa.x,sa.y), make_float2(sa.z,sa.w) };
        int sbase = (hr*24 + ky)*68 + o0;
        float4 ra = *(const float4*)&SrT[sbase];
        float4 rb = *(const float4*)&SrT[sbase + 4];
        float4 ia = *(const float4*)&SiT[sbase];
        float4 ib = *(const float4*)&SiT[sbase + 4];
        float rv[8] = { ra.x, ra.y, ra.z, ra.w, rb.x, rb.y, rb.z, rb.w };
        float iv[8] = { ia.x, ia.y, ia.z, ia.w, ib.x, ib.y, ib.z, ib.w };
        #pragma unroll
        for (int oo = 0; oo < 8; oo++) {
            float2 rd = dup2(rv[oo]);
            float2 id = dup2(iv[oo]);   // already negated
            acc[oo][0] = ffma2(rd, cv[0], acc[oo][0]);
            acc[oo][0] = ffma2(id, sv[0], acc[oo][0]);
            acc[oo][1] = ffma2(rd, cv[1], acc[oo][1]);
            acc[oo][1] = ffma2(id, sv[1], acc[oo][1]);
        }
    }

    // h1 = gelu(spec + skip); keep in regs + smem
    float h1r[8][4];
    #pragma unroll
    for (int oo = 0; oo < 8; oo++) {
        h1r[oo][0] = gelu_f(acc[oo][0].x);
        h1r[oo][1] = gelu_f(acc[oo][0].y);
        h1r[oo][2] = gelu_f(acc[oo][1].x);
        h1r[oo][3] = gelu_f(acc[oo][1].y);
        *(float4*)&h1s[hr*8192 + (o0+oo)*128 + w0] =
            make_float4(h1r[oo][0], h1r[oo][1], h1r[oo][2], h1r[oo][3]);
    }
    __syncthreads();

    // ---- phase 3: fc1 + gelu -> zs ----
    int k0 = ow * 4;
    float2 acc2[4][2];
    #pragma unroll
    for (int kk = 0; kk < 4; kk++)
        #pragma unroll
        for (int p = 0; p < 2; p++) acc2[kk][p] = make_float2(0.f, 0.f);

    const float* h1row = h1s + hr*8192;
    #pragma unroll 2
    for (int c = 0; c < 64; c++) {
        float4 ha = *(const float4*)&h1row[c*128 + w0];
        float2 hv[2] = { make_float2(ha.x,ha.y), make_float2(ha.z,ha.w) };
        float4 fv = *(const float4*)&f1wT[c*36 + k0];
        float fw[4] = { fv.x, fv.y, fv.z, fv.w };
        #pragma unroll
        for (int kk = 0; kk < 4; kk++) {
            float2 fd = dup2(fw[kk]);
            acc2[kk][0] = ffma2(fd, hv[0], acc2[kk][0]);
            acc2[kk][1] = ffma2(fd, hv[1], acc2[kk][1]);
        }
    }
    float* zs = xs;   // xs dead after phase 1
    #pragma unroll
    for (int kk = 0; kk < 4; kk++) {
        float bb = b1s[k0+kk];
        *(float4*)&zs[hr*4096 + (k0+kk)*128 + w0] = make_float4(
            gelu_f(acc2[kk][0].x + bb), gelu_f(acc2[kk][0].y + bb),
            gelu_f(acc2[kk][1].x + bb), gelu_f(acc2[kk][1].y + bb));
    }
    __syncthreads();

    // ---- phase 4: fc2 + bias + gate*h1 ----
    float2 acc3[8][2];
    #pragma unroll
    for (int oo = 0; oo < 8; oo++) {
        float bb = b2s[o0+oo];
        acc3[oo][0] = make_float2(bb, bb);
        acc3[oo][1] = make_float2(bb, bb);
    }
    const float* zrow = zs + hr*4096;
    #pragma unroll 2
    for (int k = 0; k < 32; k++) {
        float4 za = *(const float4*)&zrow[k*128 + w0];
        float2 zv[2] = { make_float2(za.x,za.y), make_float2(za.z,za.w) };
        float4 fa = *(const float4*)&f2wT[k*68 + o0];
        float4 fb = *(const float4*)&f2wT[k*68 + o0 + 4];
        float fw[8] = { fa.x, fa.y, fa.z, fa.w, fb.x, fb.y, fb.z, fb.w };
        #pragma unroll
        for (int oo = 0; oo < 8; oo++) {
            float2 fd = dup2(fw[oo]);
            acc3[oo][0] = ffma2(fd, zv[0], acc3[oo][0]);
            acc3[oo][1] = ffma2(fd, zv[1], acc3[oo][1]);
        }
    }
    #pragma unroll
    for (int oo = 0; oo < 8; oo++) {
        float g = gs[o0+oo];
        float4 r = make_float4(acc3[oo][0].x + g*h1r[oo][0],
                               acc3[oo][0].y + g*h1r[oo][1],
                               acc3[oo][1].x + g*h1r[oo][2],
                               acc3[oo][1].y + g*h1r[oo][3]);
        *(float4*)&out[(((size_t)b*64 + (o0+oo))*128 + (2*hb + hr))*128 + w0] = r;
    }
}

// ---------------- launch ----------------
extern "C" void kernel_launch(void* const* d_in, const int* in_sizes, int n_in,
                              void* d_out, int out_size) {
    const float* x    = (const float*)d_in[0];
    const float* wre  = (const float*)d_in[1];
    const float* wim  = (const float*)d_in[2];
    const float* wsk  = (const float*)d_in[3];
    const float* f1w  = (const float*)d_in[4];
    const float* f1b  = (const float*)d_in[5];
    const float* f2w  = (const float*)d_in[6];
    const float* f2b  = (const float*)d_in[7];
    const float* gate = (const float*)d_in[8];
    float* out = (float*)d_out;

    cudaFuncSetAttribute(k5_final, cudaFuncAttributeMaxDynamicSharedMemorySize,
                         SMEM_K5_FLOATS * (int)sizeof(float));

    k0_init<<<6, 512>>>();
    k1_dftW<<<1024, 384>>>(x);
    k2_dftH<<<1024, 288>>>();
    k3_mix<<<576, 512>>>(wre, wim);
    k4_idftH<<<1024, 128>>>();
    dim3 g5(64, 16);
    k5_final<<<g5, 512, SMEM_K5_FLOATS * sizeof(float)>>>(
        x, wsk, f1w, f1b, f2w, f2b, gate, out);
}

// round 4
// speedup vs baseline: 1.6226x; 1.1844x over previous
#include <cuda_runtime.h>
#include <math.h>
#include <stdint.h>

#define Bn 16
#define Cn 64
#define Hn 128
#define Wn 128
#define MXn 24
#define MYn 24
#define HIDn 32

// ---------------- scratch (device globals; no runtime allocation) ----------
__device__ float g_xw_re[Bn*Cn*Hn*MYn];       // [b][c][h][ky]
__device__ float g_xw_im[Bn*Cn*Hn*MYn];
__device__ float g_xft_re[MXn*MYn*Bn*Cn];     // [(kx*24+ky)][b][c]
__device__ float g_xft_im[MXn*MYn*Bn*Cn];
__device__ float g_oft_re[MXn*MYn*Bn*Cn];     // [(kx*24+ky)][b][o]
__device__ float g_oft_im[MXn*MYn*Bn*Cn];
__device__ float g_S_re[Bn*Hn*Cn*MYn];        // [b][h][o][ky]  (scaled)
__device__ float g_S_im[Bn*Hn*Cn*MYn];
__device__ float g_cos[MYn*Wn];               // cos(2*pi*k*w/128)
__device__ float g_sin[MYn*Wn];               // sin(2*pi*k*w/128)
__device__ float g_twT[Wn*48];                // [w][j] j<24: cos, j>=24: -sin

// ---------------- packed f32x2 helpers ----------------
__device__ __forceinline__ float2 ffma2(float2 a, float2 b, float2 c) {
    float2 r;
    asm("fma.rn.f32x2 %0, %1, %2, %3;"
        : "=l"(reinterpret_cast<unsigned long long&>(r))
        : "l"(reinterpret_cast<unsigned long long&>(a)),
          "l"(reinterpret_cast<unsigned long long&>(b)),
          "l"(reinterpret_cast<unsigned long long&>(c)));
    return r;
}
__device__ __forceinline__ float2 dup2(float x) { return make_float2(x, x); }

__device__ __forceinline__ float gelu_f(float v) {
    return 0.5f*v*(1.0f + erff(v*0.7071067811865476f));
}

// tf32 helpers
__device__ __forceinline__ float tf32f(float x) {
    uint32_t u;
    asm("cvt.rna.tf32.f32 %0, %1;" : "=r"(u) : "f"(x));
    return __uint_as_float(u);
}
__device__ __forceinline__ uint32_t fbits(float x) { return __float_as_uint(x); }

// mma.sync m16n8k8 tf32: D += A*B (D,C fp32)
__device__ __forceinline__ void mma8(float* d,
                                     uint32_t a0, uint32_t a1, uint32_t a2, uint32_t a3,
                                     uint32_t b0, uint32_t b1) {
    asm volatile(
        "mma.sync.aligned.m16n8k8.row.col.f32.tf32.tf32.f32 "
        "{%0,%1,%2,%3},{%4,%5,%6,%7},{%8,%9},{%0,%1,%2,%3};"
        : "+f"(d[0]), "+f"(d[1]), "+f"(d[2]), "+f"(d[3])
        : "r"(a0), "r"(a1), "r"(a2), "r"(a3), "r"(b0), "r"(b1));
}

// ---------------- K0: twiddle init ----------------
__global__ void k0_init() {
    int i = blockIdx.x*blockDim.x + threadIdx.x;
    if (i >= MYn*Wn) return;
    int k = i / Wn, w = i % Wn;
    float s, c;
    sincospif((float)(k*w) / 64.0f, &s, &c);
    g_cos[k*Wn + w] = c;
    g_sin[k*Wn + w] = s;
    g_twT[w*48 + k]      = c;
    g_twT[w*48 + 24 + k] = -s;
}

// ---------------- K1: partial DFT over W (ffma2 on row pairs) -------------
__global__ void __launch_bounds__(384) k1_dftW(const float* __restrict__ x) {
    __shared__ float Xs[32*132];
    __shared__ float Tw[32*48];
    int tid = threadIdx.x;
    int rg = tid & 31;
    int jg = tid >> 5;
    int row0 = blockIdx.x * 128;

    float2 acc[2][4];
    #pragma unroll
    for (int i = 0; i < 2; i++)
        #pragma unroll
        for (int j = 0; j < 4; j++) acc[i][j] = make_float2(0.f, 0.f);

    for (int kt = 0; kt < 4; kt++) {
        for (int i = tid; i < 4096; i += 384) {
            int r = i >> 5, w = i & 31;
            Xs[w*132 + r] = x[(size_t)(row0 + r)*128 + kt*32 + w];
        }
        for (int i = tid; i < 32*48; i += 384)
            Tw[i] = g_twT[kt*32*48 + i];
        __syncthreads();
        #pragma unroll
        for (int kk = 0; kk < 32; kk++) {
            float4 xa = *(const float4*)&Xs[kk*132 + 4*rg];
            float2 xp0 = make_float2(xa.x, xa.y);
            float2 xp1 = make_float2(xa.z, xa.w);
            float4 tq = *(const float4*)&Tw[kk*48 + 4*jg];
            float tv[4] = { tq.x, tq.y, tq.z, tq.w };
            #pragma unroll
            for (int j = 0; j < 4; j++) {
                float2 td = dup2(tv[j]);
                acc[0][j] = ffma2(xp0, td, acc[0][j]);
                acc[1][j] = ffma2(xp1, td, acc[1][j]);
            }
        }
        __syncthreads();
    }

    float* dst = (jg < 6) ? g_xw_re : g_xw_im;
    int col = (jg < 6) ? (4*jg) : (4*jg - 24);
    #pragma unroll
    for (int i = 0; i < 4; i++) {
        int pair = i >> 1, half = i & 1;
        float v0 = half ? acc[pair][0].y : acc[pair][0].x;
        float v1 = half ? acc[pair][1].y : acc[pair][1].x;
        float v2 = half ? acc[pair][2].y : acc[pair][2].x;
        float v3 = half ? acc[pair][3].y : acc[pair][3].x;
        int r = row0 + 4*rg + i;
        *(float4*)&dst[(size_t)r*24 + col] = make_float4(v0, v1, v2, v3);
    }
}

// ---------------- K2: partial DFT over H (ffma2 on re/im) -----------------
__global__ void __launch_bounds__(288) k2_dftH() {
    __shared__ float xr[128*24], xi[128*24];
    __shared__ float cs[24*128], sn[24*128];
    int bc = blockIdx.x;
    int tid = threadIdx.x;
    size_t base = (size_t)bc * (128*24);
    for (int i = tid; i < 3072; i += 288) {
        xr[i] = g_xw_re[base + i];
        xi[i] = g_xw_im[base + i];
        cs[i] = g_cos[i];
        sn[i] = g_sin[i];
    }
    __syncthreads();

    int ky  = tid % 24;
    int kxg = tid / 24;
    int kx0 = 2*kxg, kx1 = 2*kxg + 1;
    float2 acc0 = make_float2(0.f, 0.f);
    float2 acc1 = make_float2(0.f, 0.f);
    #pragma unroll 4
    for (int h = 0; h < 128; h++) {
        float a = xr[h*24 + ky];
        float b = xi[h*24 + ky];
        float2 ab  = make_float2(a, b);
        float2 bna = make_float2(b, -a);
        acc0 = ffma2(ab,  dup2(cs[kx0*128 + h]), acc0);
        acc0 = ffma2(bna, dup2(sn[kx0*128 + h]), acc0);
        acc1 = ffma2(ab,  dup2(cs[kx1*128 + h]), acc1);
        acc1 = ffma2(bna, dup2(sn[kx1*128 + h]), acc1);
    }
    int b = bc >> 6, c = bc & 63;
    int m0 = kx0*24 + ky, m1 = kx1*24 + ky;
    g_xft_re[(m0*Bn + b)*Cn + c] = acc0.x;
    g_xft_im[(m0*Bn + b)*Cn + c] = acc0.y;
    g_xft_re[(m1*Bn + b)*Cn + c] = acc1.x;
    g_xft_im[(m1*Bn + b)*Cn + c] = acc1.y;
}

// ---------------- K3: per-mode complex channel mix (512 thr) --------------
__global__ void __launch_bounds__(512) k3_mix(const float* __restrict__ wr_g,
                                              const float* __restrict__ wi_g) {
    __shared__ float xr_s[1024], xi_s[1024];
    __shared__ float wr_s[4096], wi_s[4096];
    int m = blockIdx.x, tid = threadIdx.x;
    for (int i = tid; i < 1024; i += 512) {
        xr_s[i] = g_xft_re[m*1024 + i];
        xi_s[i] = g_xft_im[m*1024 + i];
    }
    for (int i = tid; i < 4096; i += 512) {
        wr_s[i] = wr_g[(size_t)m*4096 + i];
        wi_s[i] = wi_g[(size_t)m*4096 + i];
    }
    __syncthreads();

    int b  = tid >> 5;
    int og = tid & 31;
    float2 re = make_float2(0.f, 0.f), im = make_float2(0.f, 0.f);
    #pragma unroll 4
    for (int c = 0; c < 64; c++) {
        float xr = xr_s[b*64 + c];
        float xi = xi_s[b*64 + c];
        float2 wr = *(const float2*)&wr_s[c*64 + 2*og];
        float2 wi = *(const float2*)&wi_s[c*64 + 2*og];
        re = ffma2(dup2(xr),  wr, re);
        re = ffma2(dup2(-xi), wi, re);
        im = ffma2(dup2(xr),  wi, im);
        im = ffma2(dup2(xi),  wr, im);
    }
    int base = (m*Bn + b)*Cn + 2*og;
    *(float2*)&g_oft_re[base] = re;
    *(float2*)&g_oft_im[base] = im;
}

// ---------------- K4: inverse DFT over H (ffma2 on ar/ai) -----------------
__global__ void __launch_bounds__(128) k4_idftH() {
    __shared__ float osm[576*2];
    __shared__ float cs[24*128], sn[24*128];
    int bx = blockIdx.x;
    int b = bx >> 6, o = bx & 63;
    int tid = threadIdx.x;
    for (int i = tid; i < 576; i += 128) {
        osm[2*i]   = g_oft_re[i*1024 + b*64 + o];
        osm[2*i+1] = g_oft_im[i*1024 + b*64 + o];
    }
    for (int i = tid; i < 3072; i += 128) { cs[i] = g_cos[i]; sn[i] = g_sin[i]; }
    __syncthreads();

    int h = tid;
    float2 acc[24];
    #pragma unroll
    for (int ky = 0; ky < 24; ky++) acc[ky] = make_float2(0.f, 0.f);
    #pragma unroll 2
    for (int kx = 0; kx < 24; kx++) {
        float cr = cs[kx*128 + h];
        float si = sn[kx*128 + h];
        float2 v1 = make_float2(cr, si);
        float2 v2 = make_float2(-si, cr);
        #pragma unroll
        for (int ky = 0; ky < 24; ky++) {
            float2 ov = *(const float2*)&osm[(kx*24 + ky)*2];
            acc[ky] = ffma2(dup2(ov.x), v1, acc[ky]);
            acc[ky] = ffma2(dup2(ov.y), v2, acc[ky]);
        }
    }
    size_t base = (((size_t)b*128 + h)*64 + o)*24;
    const float sc = 1.0f/16384.0f;
    #pragma unroll
    for (int ky = 0; ky < 24; ky++) {
        float s = (ky == 0) ? sc : 2.0f*sc;
        g_S_re[base + ky] = acc[ky].x*s;
        g_S_im[base + ky] = acc[ky].y*s;
    }
}

// ---------------- K5: fused final via mma.sync tf32 -----------------------
// smem layout (floats):
//   xs   [2][64][136]  17408   (rows reused as zs: zs[hr] = xs + hr*4352, [32][136])
//   h1s  [2][64][136]  17408   (reused as output staging after phase3)
//   wskA [64][72]       4608   (k-permuted tf32)
//   SrA  [2][64][28]    3584   (tf32)
//   SiA  [2][64][28]    3584   (tf32, negated)
//   trig [48][136]      6528   (rows 0-23 cos, 24-47 sin; tf32)
//   f1A  [32][72]       2304   (k-permuted tf32)
//   f2A  [64][36]       2304   (k-permuted tf32)
//   b1s 32, b2s 64, gs 64
#define K5_SMEM_FLOATS 57888
#define SX 136

__global__ void __launch_bounds__(512, 1) k5_final(
    const float* __restrict__ x,
    const float* __restrict__ wsk_g,
    const float* __restrict__ f1w_g, const float* __restrict__ f1b_g,
    const float* __restrict__ f2w_g, const float* __restrict__ f2b_g,
    const float* __restrict__ gate_g,
    float* __restrict__ out)
{
    extern __shared__ float sm[];
    float* xs   = sm;
    float* h1s  = sm + 17408;
    float* wskA = sm + 34816;
    float* SrA  = sm + 39424;
    float* SiA  = sm + 43008;
    float* trig = sm + 46592;
    float* f1A  = sm + 53120;
    float* f2A  = sm + 55424;
    float* b1s  = sm + 57728;
    float* b2s  = sm + 57760;
    float* gs   = sm + 57824;

    int tid  = threadIdx.x;
    int lane = tid & 31;
    int wid  = tid >> 5;          // 0..15
    int hr   = wid >> 3;          // row within block
    int w8   = wid & 7;
    int p    = w8 & 1;            // m-pair (rows 32p..32p+31)
    int q    = w8 >> 1;           // n-quad (cols 32q..32q+31)
    int qr   = lane >> 2;         // 0..7
    int qc   = lane & 3;          // 0..3
    int hb = blockIdx.x;          // rows 2*hb, 2*hb+1
    int b  = blockIdx.y;

    // ---- cooperative loads (all tf32-converted) ----
    for (int i = tid; i < 4096; i += 512) {
        int hh = i >> 11, c = (i >> 5) & 63, w = (i & 31) * 4;
        float4 v = *(const float4*)&x[(((size_t)b*64 + c)*128 + (2*hb + hh))*128 + w];
        v.x = tf32f(v.x); v.y = tf32f(v.y); v.z = tf32f(v.z); v.w = tf32f(v.w);
        *(float4*)&xs[hh*8704 + c*SX + w] = v;
    }
    for (int i = tid; i < 6144; i += 512) {
        int r = i >> 7, w = i & 127;
        float v = (r < 24) ? g_cos[r*128 + w] : g_sin[(r-24)*128 + w];
        trig[r*SX + w] = tf32f(v);
    }
    for (int i = tid; i < 4096; i += 512) {
        int o = i >> 6, c = i & 63;
        int cp = (c & ~7) + ((c & 3) << 1) + ((c >> 2) & 1);
        wskA[o*72 + cp] = tf32f(wsk_g[i]);
    }
    {
        size_t sb = ((size_t)b*128 + 2*hb) * (64*24);
        for (int i = tid; i < 3072; i += 512) {
            int hh = i / 1536, j = i - hh*1536;
            int o = j / 24, ky = j - o*24;
            SrA[hh*1792 + o*28 + ky] = tf32f( g_S_re[sb + (size_t)hh*1536 + j]);
            SiA[hh*1792 + o*28 + ky] = tf32f(-g_S_im[sb + (size_t)hh*1536 + j]);
        }
    }
    for (int i = tid; i < 2048; i += 512) {
        int k = i >> 6, c = i & 63;
        int cp = (c & ~7) + ((c & 3) << 1) + ((c >> 2) & 1);
        f1A[k*72 + cp] = tf32f(f1w_g[i]);
    }
    for (int i = tid; i < 2048; i += 512) {
        int o = i >> 5, k = i & 31;
        int kp = (k & ~7) + ((k & 3) << 1) + ((k >> 2) & 1);
        f2A[o*36 + kp] = tf32f(f2w_g[i]);
    }
    if (tid < 32) b1s[tid] = f1b_g[tid];
    if (tid < 64) { b2s[tid] = f2b_g[tid]; gs[tid] = gate_g[tid]; }
    __syncthreads();

    const float* xrow  = xs  + hr*8704;
    const float* h1row = h1s + hr*8704;

    // ================= phase 1+2: skip GEMM + spectral GEMM =================
    float d1[2][4][4];
    #pragma unroll
    for (int t = 0; t < 2; t++)
        #pragma unroll
        for (int j = 0; j < 4; j++)
            #pragma unroll
            for (int e = 0; e < 4; e++) d1[t][j][e] = 0.f;

    // skip: K = 64 over channels
    #pragma unroll
    for (int ks = 0; ks < 8; ks++) {
        int k0 = ks * 8;
        uint32_t a[2][4];
        #pragma unroll
        for (int t = 0; t < 2; t++) {
            int R = 32*p + 16*t;
            float2 lo = *(const float2*)&wskA[(R+qr)*72 + k0 + 2*qc];
            float2 hi = *(const float2*)&wskA[(R+qr+8)*72 + k0 + 2*qc];
            a[t][0] = fbits(lo.x); a[t][1] = fbits(hi.x);
            a[t][2] = fbits(lo.y); a[t][3] = fbits(hi.y);
        }
        #pragma unroll
        for (int j = 0; j < 4; j++) {
            int N = 32*q + 8*j;
            uint32_t b0 = fbits(xrow[(k0+qc)*SX + N + qr]);
            uint32_t b1 = fbits(xrow[(k0+qc+4)*SX + N + qr]);
            mma8(d1[0][j], a[0][0], a[0][1], a[0][2], a[0][3], b0, b1);
            mma8(d1[1][j], a[1][0], a[1][1], a[1][2], a[1][3], b0, b1);
        }
    }
    // spectral: K = 24 (cos) + 24 (sin, A pre-negated)
    const float* Sr_ = SrA + hr*1792;
    const float* Si_ = SiA + hr*1792;
    #pragma unroll
    for (int ks = 0; ks < 3; ks++) {
        int k0 = ks * 8;
        uint32_t ar[2][4], ai[2][4];
        #pragma unroll
        for (int t = 0; t < 2; t++) {
            int R = 32*p + 16*t;
            ar[t][0] = fbits(Sr_[(R+qr)*28   + k0 + qc]);
            ar[t][1] = fbits(Sr_[(R+qr+8)*28 + k0 + qc]);
            ar[t][2] = fbits(Sr_[(R+qr)*28   + k0 + qc + 4]);
            ar[t][3] = fbits(Sr_[(R+qr+8)*28 + k0 + qc + 4]);
            ai[t][0] = fbits(Si_[(R+qr)*28   + k0 + qc]);
            ai[t][1] = fbits(Si_[(R+qr+8)*28 + k0 + qc]);
            ai[t][2] = fbits(Si_[(R+qr)*28   + k0 + qc + 4]);
            ai[t][3] = fbits(Si_[(R+qr+8)*28 + k0 + qc + 4]);
        }
        #pragma unroll
        for (int j = 0; j < 4; j++) {
            int N = 32*q + 8*j;
            uint32_t c0 = fbits(trig[(k0+qc)*SX      + N + qr]);
            uint32_t c1 = fbits(trig[(k0+qc+4)*SX    + N + qr]);
            uint32_t s0 = fbits(trig[(24+k0+qc)*SX   + N + qr]);
            uint32_t s1 = fbits(trig[(24+k0+qc+4)*SX + N + qr]);
            mma8(d1[0][j], ar[0][0], ar[0][1], ar[0][2], ar[0][3], c0, c1);
            mma8(d1[1][j], ar[1][0], ar[1][1], ar[1][2], ar[1][3], c0, c1);
            mma8(d1[0][j], ai[0][0], ai[0][1], ai[0][2], ai[0][3], s0, s1);
            mma8(d1[1][j], ai[1][0], ai[1][1], ai[1][2], ai[1][3], s0, s1);
        }
    }

    // gelu -> h1 (fp32 kept in regs for gate; tf32 copy to smem)
    float h1r[2][4][4];
    #pragma unroll
    for (int t = 0; t < 2; t++) {
        int row0 = 32*p + 16*t + qr;
        #pragma unroll
        for (int j = 0; j < 4; j++) {
            int N = 32*q + 8*j;
            #pragma unroll
            for (int e = 0; e < 4; e++) h1r[t][j][e] = gelu_f(d1[t][j][e]);
            *(float2*)&h1s[hr*8704 + row0*SX + N + 2*qc] =
                make_float2(tf32f(h1r[t][j][0]), tf32f(h1r[t][j][1]));
            *(float2*)&h1s[hr*8704 + (row0+8)*SX + N + 2*qc] =
                make_float2(tf32f(h1r[t][j][2]), tf32f(h1r[t][j][3]));
        }
    }
    __syncthreads();

    // ================= phase 3: fc1 + gelu -> zs ============================
    float d3[2][2][4];
    #pragma unroll
    for (int t = 0; t < 2; t++)
        #pragma unroll
        for (int j = 0; j < 2; j++)
            #pragma unroll
            for (int e = 0; e < 4; e++) d3[t][j][e] = 0.f;

    #pragma unroll
    for (int ks = 0; ks < 8; ks++) {
        int k0 = ks * 8;
        uint32_t a[2][4];
        #pragma unroll
        for (int t = 0; t < 2; t++) {
            int R = 16*t;
            float2 lo = *(const float2*)&f1A[(R+qr)*72 + k0 + 2*qc];
            float2 hi = *(const float2*)&f1A[(R+qr+8)*72 + k0 + 2*qc];
            a[t][0] = fbits(lo.x); a[t][1] = fbits(hi.x);
            a[t][2] = fbits(lo.y); a[t][3] = fbits(hi.y);
        }
        #pragma unroll
        for (int j = 0; j < 2; j++) {
            int N3 = 16*w8 + 8*j;
            uint32_t b0 = fbits(h1row[(k0+qc)*SX + N3 + qr]);
            uint32_t b1 = fbits(h1row[(k0+qc+4)*SX + N3 + qr]);
            mma8(d3[0][j], a[0][0], a[0][1], a[0][2], a[0][3], b0, b1);
            mma8(d3[1][j], a[1][0], a[1][1], a[1][2], a[1][3], b0, b1);
        }
    }
    float* zrow = xs + hr*4352;   // alias: xs dead after phase1 reads
    #pragma unroll
    for (int t = 0; t < 2; t++) {
        int row0 = 16*t + qr;
        float bb0 = b1s[row0], bb8 = b1s[row0+8];
        #pragma unroll
        for (int j = 0; j < 2; j++) {
            int N3 = 16*w8 + 8*j;
            *(float2*)&zrow[row0*SX + N3 + 2*qc] =
                make_float2(tf32f(gelu_f(d3[t][j][0] + bb0)),
                            tf32f(gelu_f(d3[t][j][1] + bb0)));
            *(float2*)&zrow[(row0+8)*SX + N3 + 2*qc] =
                make_float2(tf32f(gelu_f(d3[t][j][2] + bb8)),
                            tf32f(gelu_f(d3[t][j][3] + bb8)));
        }
    }
    __syncthreads();

    // ================= phase 4: fc2 + bias + gate*h1 ========================
    float d4[2][4][4];
    #pragma unroll
    for (int t = 0; t < 2; t++) {
        int row0 = 32*p + 16*t + qr;
        float bb0 = b2s[row0], bb8 = b2s[row0+8];
        #pragma unroll
        for (int j = 0; j < 4; j++) {
            d4[t][j][0] = bb0; d4[t][j][1] = bb0;
            d4[t][j][2] = bb8; d4[t][j][3] = bb8;
        }
    }
    #pragma unroll
    for (int ks = 0; ks < 4; ks++) {
        int k0 = ks * 8;
        uint32_t a[2][4];
        #pragma unroll
        for (int t = 0; t < 2; t++) {
            int R = 32*p + 16*t;
            float2 lo = *(const float2*)&f2A[(R+qr)*36 + k0 + 2*qc];
            float2 hi = *(const float2*)&f2A[(R+qr+8)*36 + k0 + 2*qc];
            a[t][0] = fbits(lo.x); a[t][1] = fbits(hi.x);
            a[t][2] = fbits(lo.y); a[t][3] = fbits(hi.y);
        }
        #pragma unroll
        for (int j = 0; j < 4; j++) {
            int N = 32*q + 8*j;
            uint32_t b0 = fbits(zrow[(k0+qc)*SX + N + qr]);
            uint32_t b1 = fbits(zrow[(k0+qc+4)*SX + N + qr]);
            mma8(d4[0][j], a[0][0], a[0][1], a[0][2], a[0][3], b0, b1);
            mma8(d4[1][j], a[1][0], a[1][1], a[1][2], a[1][3], b0, b1);
        }
    }
    // gate add, stage into h1s (free after phase3 reads)
    #pragma unroll
    for (int t = 0; t < 2; t++) {
        int row0 = 32*p + 16*t + qr;
        float g0 = gs[row0], g8 = gs[row0+8];
        #pragma unroll
        for (int j = 0; j < 4; j++) {
            int N = 32*q + 8*j;
            *(float2*)&h1s[hr*8704 + row0*SX + N + 2*qc] =
                make_float2(d4[t][j][0] + g0*h1r[t][j][0],
                            d4[t][j][1] + g0*h1r[t][j][1]);
            *(float2*)&h1s[hr*8704 + (row0+8)*SX + N + 2*qc] =
                make_float2(d4[t][j][2] + g8*h1r[t][j][2],
                            d4[t][j][3] + g8*h1r[t][j][3]);
        }
    }
    __syncthreads();

    // coalesced final store
    for (int i = tid; i < 4096; i += 512) {
        int hh = i >> 11, c = (i >> 5) & 63, w = (i & 31) * 4;
        float4 v = *(const float4*)&h1s[hh*8704 + c*SX + w];
        *(float4*)&out[(((size_t)b*64 + c)*128 + (2*hb + hh))*128 + w] = v;
    }
}

// ---------------- launch ----------------
extern "C" void kernel_launch(void* const* d_in, const int* in_sizes, int n_in,
                              void* d_out, int out_size) {
    const float* x    = (const float*)d_in[0];
    const float* wre  = (const float*)d_in[1];
    const float* wim  = (const float*)d_in[2];
    const float* wsk  = (const float*)d_in[3];
    const float* f1w  = (const float*)d_in[4];
    const float* f1b  = (const float*)d_in[5];
    const float* f2w  = (const float*)d_in[6];
    const float* f2b  = (const float*)d_in[7];
    const float* gate = (const float*)d_in[8];
    float* out = (float*)d_out;

    cudaFuncSetAttribute(k5_final, cudaFuncAttributeMaxDynamicSharedMemorySize,
                         K5_SMEM_FLOATS * (int)sizeof(float));

    k0_init<<<6, 512>>>();
    k1_dftW<<<1024, 384>>>(x);
    k2_dftH<<<1024, 288>>>();
    k3_mix<<<576, 512>>>(wre, wim);
    k4_idftH<<<1024, 128>>>();
    dim3 g5(64, 16);
    k5_final<<<g5, 512, K5_SMEM_FLOATS * sizeof(float)>>>(
        x, wsk, f1w, f1b, f2w, f2b, gate, out);
}